// round 8
// baseline (speedup 1.0000x reference)
#include <cuda_runtime.h>
#include <cuda_fp16.h>
#include <cstdint>

#define IN_F     4096
#define OUT_F    4096
#define N_TOK    8192
#define GROUP    128
#define NGROUPS  (IN_F / GROUP)
#define N_STAGES 4
#define QMAXF    15.0f

// ---------------- scratch (device globals; no runtime allocation) ----------
__device__ __half g_w_h[(size_t)OUT_F * IN_F];
__device__ __half g_x_h[(size_t)N_TOK * IN_F];

// ---------------------------------------------------------------------------
// Kernel 0: x -> fp16 (8 elems/thread, 16B stores)  [measured: DRAM-floor]
// ---------------------------------------------------------------------------
__global__ __launch_bounds__(256) void convert_x_kernel(const float* __restrict__ x)
{
    size_t i = ((size_t)blockIdx.x * 256 + threadIdx.x) * 8;
    float4 v0 = *reinterpret_cast<const float4*>(x + i);
    float4 v1 = *reinterpret_cast<const float4*>(x + i + 4);
    __half2 h[4];
    h[0] = __floats2half2_rn(v0.x, v0.y);
    h[1] = __floats2half2_rn(v0.z, v0.w);
    h[2] = __floats2half2_rn(v1.x, v1.y);
    h[3] = __floats2half2_rn(v1.z, v1.w);
    *reinterpret_cast<uint4*>(g_x_h + i) = *reinterpret_cast<const uint4*>(h);
}

// ---------------------------------------------------------------------------
// Kernel 1: warp-synchronous weight transform.
// Block = (group g, 64 rows); each of 8 warps owns 8 rows sequentially.
// Row lives in a warp-private 128-float smem buffer; stages separated by
// __syncwarp only. One __syncthreads total (table load).
// ---------------------------------------------------------------------------
#define ROWS_PB 64

__global__ __launch_bounds__(256) void transform_kernel(
    const float* __restrict__ weight,
    const float* __restrict__ channel_scales,
    const float* __restrict__ theta,
    const float* __restrict__ q_scale,
    const float* __restrict__ q_zp,
    const int*   __restrict__ pairs)
{
    const int g    = blockIdx.x;              // 0..31
    const int row0 = blockIdx.y * ROWS_PB;
    const int tid  = threadIdx.x;
    const int wrp  = tid >> 5;                // 0..7
    const int lane = tid & 31;

    __shared__ float cs_c[N_STAGES][64], cs_s[N_STAGES][64];
    __shared__ int   pi[N_STAGES][64], pj[N_STAGES][64];
    __shared__ float csc[GROUP];
    __shared__ float wbuf[8][GROUP];          // per-warp row buffer

    if (tid < GROUP) csc[tid] = channel_scales[g * GROUP + tid];
    {
        int st = tid >> 6, p = tid & 63;      // 256 threads = 4 stages x 64 pairs
        float s, c;
        sincosf(theta[st * (IN_F / 2) + g * 64 + p], &s, &c);
        cs_c[st][p] = c;
        cs_s[st][p] = s;
        pi[st][p] = pairs[st * IN_F + g * GROUP + 2 * p];
        pj[st][p] = pairs[st * IN_F + g * GROUP + 2 * p + 1];
    }
    __syncthreads();

    float* wb = wbuf[wrp];
    const int c4 = lane * 4;

    #pragma unroll 1
    for (int rr = 0; rr < ROWS_PB / 8; rr++) {
        const int row = row0 + wrp * 8 + rr;

        // load + channel scale
        float4 v = *reinterpret_cast<const float4*>(
            weight + (size_t)row * IN_F + g * GROUP + c4);
        v.x *= csc[c4];
        v.y *= csc[c4 + 1];
        v.z *= csc[c4 + 2];
        v.w *= csc[c4 + 3];
        *reinterpret_cast<float4*>(&wb[c4]) = v;
        __syncwarp();

        // forward rotations (2 disjoint pairs per lane per stage)
        #pragma unroll
        for (int st = 0; st < N_STAGES; st++) {
            #pragma unroll
            for (int q = 0; q < 2; q++) {
                int p = lane + q * 32;
                float c = cs_c[st][p], s = cs_s[st][p];
                int i = pi[st][p], j = pj[st][p];
                float xi = wb[i], xj = wb[j];
                wb[i] =  xi * c + xj * s;
                wb[j] = -xi * s + xj * c;
            }
            __syncwarp();
        }

        // quant-dequant (elementwise; same scalar for whole row-group)
        {
            int gi = row * NGROUPS + g;
            float s   = fminf(fmaxf(q_scale[gi], 1e-5f), 1e5f);
            float rzp = fminf(fmaxf(-rintf(q_zp[gi]), 0.0f), QMAXF);
            #pragma unroll
            for (int e = 0; e < 4; e++) {
                float q = rintf(wb[c4 + e] / s) + rzp;
                q = fminf(fmaxf(q, 0.0f), QMAXF);
                wb[c4 + e] = (q - rzp) * s;
            }
        }
        __syncwarp();

        // inverse rotations
        #pragma unroll
        for (int st = N_STAGES - 1; st >= 0; st--) {
            #pragma unroll
            for (int q = 0; q < 2; q++) {
                int p = lane + q * 32;
                float c = cs_c[st][p], s = cs_s[st][p];
                int i = pi[st][p], j = pj[st][p];
                float xi = wb[i], xj = wb[j];
                wb[i] = xi * c - xj * s;
                wb[j] = xi * s + xj * c;
            }
            __syncwarp();
        }

        // unscale + fp16 store (8B per lane, coalesced)
        __half2 h[2];
        h[0] = __floats2half2_rn(wb[c4]     / csc[c4],
                                 wb[c4 + 1] / csc[c4 + 1]);
        h[1] = __floats2half2_rn(wb[c4 + 2] / csc[c4 + 2],
                                 wb[c4 + 3] / csc[c4 + 3]);
        *reinterpret_cast<uint2*>(
            g_w_h + (size_t)row * IN_F + g * GROUP + c4) =
            *reinterpret_cast<const uint2*>(h);
        __syncwarp();
    }
}

// ---------------------------------------------------------------------------
// Kernel 2: fp16 mma.sync GEMM (unchanged from R7; measured-stable 646us).
// CTA 128x256, 512 threads, warp tile 64x32, BK=64, 4-stage cp.async.
// ---------------------------------------------------------------------------
#define BM 128
#define BN 256
#define BK 64
#define KSTAGES 4
#define NTHREADS 512
#define A_STAGE_BYTES (BM * BK * 2)
#define B_STAGE_BYTES (BN * BK * 2)
#define STAGE_BYTES   (A_STAGE_BYTES + B_STAGE_BYTES)
#define GEMM_SMEM     (KSTAGES * STAGE_BYTES)            // 196608
#define NKT           (IN_F / BK)                        // 64

__device__ __forceinline__ uint32_t smem_u32(const void* p) {
    uint32_t a;
    asm("{ .reg .u64 t; cvta.to.shared.u64 t, %1; cvt.u32.u64 %0, t; }"
        : "=r"(a) : "l"(p));
    return a;
}
__device__ __forceinline__ void cp_async16(uint32_t saddr, const void* gptr) {
    asm volatile("cp.async.cg.shared.global [%0], [%1], 16;"
                 :: "r"(saddr), "l"(gptr));
}
#define CP_COMMIT() asm volatile("cp.async.commit_group;" ::: "memory")
#define CP_WAIT(n)  asm volatile("cp.async.wait_group %0;" :: "n"(n) : "memory")

__device__ __forceinline__ void ldmatrix_x4(uint32_t* r, uint32_t addr) {
    asm volatile("ldmatrix.sync.aligned.m8n8.x4.shared.b16 {%0,%1,%2,%3}, [%4];"
                 : "=r"(r[0]), "=r"(r[1]), "=r"(r[2]), "=r"(r[3]) : "r"(addr));
}
__device__ __forceinline__ void mma16816(float* c, const uint32_t* a,
                                         const uint32_t* b) {
    asm volatile("mma.sync.aligned.m16n8k16.row.col.f32.f16.f16.f32 "
                 "{%0,%1,%2,%3}, {%4,%5,%6,%7}, {%8,%9}, {%0,%1,%2,%3};"
                 : "+f"(c[0]), "+f"(c[1]), "+f"(c[2]), "+f"(c[3])
                 : "r"(a[0]), "r"(a[1]), "r"(a[2]), "r"(a[3]),
                   "r"(b[0]), "r"(b[1]));
}

__global__ __launch_bounds__(NTHREADS, 1) void gemm_mma_kernel(
    const float* __restrict__ bias, float* __restrict__ C)
{
    extern __shared__ char smem[];
    const uint32_t sbase = smem_u32(smem);
    const int tid  = threadIdx.x;
    const int wid  = tid >> 5;
    const int lane = tid & 31;
    const int bn = blockIdx.x;
    const int bm = blockIdx.y;
    const int warp_m = wid >> 3;
    const int warp_n = wid & 7;

    const __half* Ag0 = g_x_h + (size_t)(bm * BM) * IN_F;
    const __half* Bg0 = g_w_h + (size_t)(bn * BN) * IN_F;

    float acc[4][4][4];
    #pragma unroll
    for (int i = 0; i < 4; i++)
        #pragma unroll
        for (int j = 0; j < 4; j++)
            #pragma unroll
            for (int k = 0; k < 4; k++) acc[i][j][k] = 0.0f;

    auto load_stage = [&](int kt) {
        const int buf = kt & (KSTAGES - 1);
        const int ko  = kt * BK;
        const __half* Ag = Ag0 + ko;
        const __half* Bg = Bg0 + ko;
        const uint32_t sA = sbase + buf * STAGE_BYTES;
        const uint32_t sB = sA + A_STAGE_BYTES;
        #pragma unroll
        for (int t = 0; t < 2; t++) {
            int v = tid + t * NTHREADS;
            int r = v >> 3, c = v & 7;
            uint32_t off = (uint32_t)(r << 7) + (uint32_t)((c ^ (r & 7)) << 4);
            cp_async16(sA + off, Ag + (size_t)r * IN_F + c * 8);
        }
        #pragma unroll
        for (int t = 0; t < 4; t++) {
            int v = tid + t * NTHREADS;
            int r = v >> 3, c = v & 7;
            uint32_t off = (uint32_t)(r << 7) + (uint32_t)((c ^ (r & 7)) << 4);
            cp_async16(sB + off, Bg + (size_t)r * IN_F + c * 8);
        }
    };

    const int m_lane  = warp_m * 64 + (lane & 15);
    const int a_half  = lane >> 4;
    const int xa      = m_lane & 7;
    const int n_lane  = warp_n * 32 + (lane & 7) + ((lane >> 4) << 3);
    const int b_half  = (lane >> 3) & 1;
    const int xb      = n_lane & 7;

    #pragma unroll
    for (int s = 0; s < KSTAGES - 1; s++) {
        load_stage(s);
        CP_COMMIT();
    }

    for (int kt = 0; kt < NKT; kt++) {
        CP_WAIT(KSTAGES - 2);
        __syncthreads();

        if (kt + KSTAGES - 1 < NKT) load_stage(kt + KSTAGES - 1);
        CP_COMMIT();

        const int buf = kt & (KSTAGES - 1);
        const uint32_t sA = sbase + buf * STAGE_BYTES;
        const uint32_t sB = sA + A_STAGE_BYTES;
        const uint32_t aRow = sA + (uint32_t)(m_lane << 7);
        const uint32_t bRow = sB + (uint32_t)(n_lane << 7);

        #pragma unroll
        for (int kk = 0; kk < 4; kk++) {
            uint32_t a_frag[4][4];
            uint32_t b_frag[2][4];
            const uint32_t ac = (uint32_t)(((kk * 2 + a_half) ^ xa) << 4);
            const uint32_t bc = (uint32_t)(((kk * 2 + b_half) ^ xb) << 4);
            #pragma unroll
            for (int mt = 0; mt < 4; mt++)
                ldmatrix_x4(a_frag[mt], aRow + (uint32_t)(mt << 11) + ac);
            #pragma unroll
            for (int nt = 0; nt < 2; nt++)
                ldmatrix_x4(b_frag[nt], bRow + (uint32_t)(nt << 11) + bc);
            #pragma unroll
            for (int mt = 0; mt < 4; mt++) {
                #pragma unroll
                for (int nt = 0; nt < 2; nt++) {
                    mma16816(acc[mt][2 * nt],     a_frag[mt], &b_frag[nt][0]);
                    mma16816(acc[mt][2 * nt + 1], a_frag[mt], &b_frag[nt][2]);
                }
            }
        }
    }

    const int row_base = bm * BM + warp_m * 64 + (lane >> 2);
    const int col_base = bn * BN + warp_n * 32 + 2 * (lane & 3);
    #pragma unroll
    for (int mt = 0; mt < 4; mt++) {
        const int r0 = row_base + mt * 16;
        #pragma unroll
        for (int n8 = 0; n8 < 4; n8++) {
            const int col = col_base + n8 * 8;
            float2 bv = *reinterpret_cast<const float2*>(bias + col);
            float2 o0, o1;
            o0.x = acc[mt][n8][0] + bv.x;
            o0.y = acc[mt][n8][1] + bv.y;
            o1.x = acc[mt][n8][2] + bv.x;
            o1.y = acc[mt][n8][3] + bv.y;
            *reinterpret_cast<float2*>(C + (size_t)r0 * OUT_F + col)       = o0;
            *reinterpret_cast<float2*>(C + (size_t)(r0 + 8) * OUT_F + col) = o1;
        }
    }
}

// ---------------------------------------------------------------------------
// Launch
// ---------------------------------------------------------------------------
extern "C" void kernel_launch(void* const* d_in, const int* in_sizes, int n_in,
                              void* d_out, int out_size)
{
    const float* x              = (const float*)d_in[0];
    const float* weight         = (const float*)d_in[1];
    const float* bias           = (const float*)d_in[2];
    const float* channel_scales = (const float*)d_in[3];
    const float* theta          = (const float*)d_in[4];
    const float* q_scale        = (const float*)d_in[5];
    const float* q_zp           = (const float*)d_in[6];
    const int*   pairs          = (const int*)d_in[7];
    float* out = (float*)d_out;

    cudaFuncSetAttribute(gemm_mma_kernel,
                         cudaFuncAttributeMaxDynamicSharedMemorySize, GEMM_SMEM);

    convert_x_kernel<<<(size_t)N_TOK * IN_F / 8 / 256, 256>>>(x);

    dim3 tgrid(NGROUPS, OUT_F / ROWS_PB);
    transform_kernel<<<tgrid, 256>>>(weight, channel_scales, theta,
                                     q_scale, q_zp, pairs);

    dim3 grid(OUT_F / BN, N_TOK / BM);
    gemm_mma_kernel<<<grid, NTHREADS, GEMM_SMEM>>>(bias, out);
}

// round 9
// speedup vs baseline: 1.0637x; 1.0637x over previous
#include <cuda_runtime.h>
#include <cuda_fp16.h>
#include <cstdint>

#define IN_F     4096
#define OUT_F    4096
#define N_TOK    8192
#define GROUP    128
#define NGROUPS  (IN_F / GROUP)
#define N_STAGES 4
#define QMAXF    15.0f

// ---------------- scratch (device globals; no runtime allocation) ----------
__device__ __half g_w_h[(size_t)OUT_F * IN_F];
__device__ __half g_x_h[(size_t)N_TOK * IN_F];

// ---------------------------------------------------------------------------
// Kernel 1: fused weight transform + x->fp16 conversion.
// Transform: block = (group g, 64 rows), R7 block-sync structure (high ILP).
// Conversion: each block converts a disjoint 16384-elem slice of x before the
// first barrier, overlapping the pure-DRAM stream with the transform's
// latency/barrier slack.
// ---------------------------------------------------------------------------
#define ROWS_PB 64
#define WPAD    132
#define TBLOCKS (NGROUPS * (OUT_F / ROWS_PB))          // 2048
#define XCHUNK  ((size_t)N_TOK * IN_F / TBLOCKS)       // 16384 elems / block

__global__ __launch_bounds__(256) void transform_kernel(
    const float* __restrict__ weight,
    const float* __restrict__ channel_scales,
    const float* __restrict__ theta,
    const float* __restrict__ q_scale,
    const float* __restrict__ q_zp,
    const int*   __restrict__ pairs,
    const float* __restrict__ x)
{
    const int g    = blockIdx.x;
    const int row0 = blockIdx.y * ROWS_PB;
    const int tid  = threadIdx.x;

    __shared__ float w[ROWS_PB][WPAD];
    __shared__ float cs_c[N_STAGES][64], cs_s[N_STAGES][64];
    __shared__ int   pi[N_STAGES][64], pj[N_STAGES][64];
    __shared__ float csc[GROUP];
    __shared__ float qs[ROWS_PB], qz[ROWS_PB];

    // ---- fused x -> fp16 conversion (independent of everything below) ----
    {
        const int blk = blockIdx.y * NGROUPS + blockIdx.x;  // 0..2047
        const float* xs = x + (size_t)blk * XCHUNK;
        __half* xd = g_x_h + (size_t)blk * XCHUNK;
        #pragma unroll
        for (int t = 0; t < (int)(XCHUNK / (256 * 8)); t++) {   // 8 iters
            size_t i = ((size_t)(t * 256 + tid)) * 8;
            float4 v0 = *reinterpret_cast<const float4*>(xs + i);
            float4 v1 = *reinterpret_cast<const float4*>(xs + i + 4);
            __half2 h[4];
            h[0] = __floats2half2_rn(v0.x, v0.y);
            h[1] = __floats2half2_rn(v0.z, v0.w);
            h[2] = __floats2half2_rn(v1.x, v1.y);
            h[3] = __floats2half2_rn(v1.z, v1.w);
            *reinterpret_cast<uint4*>(xd + i) =
                *reinterpret_cast<const uint4*>(h);
        }
    }

    // ---- tables ----
    if (tid < GROUP) csc[tid] = channel_scales[g * GROUP + tid];
    {
        int st = tid >> 6, p = tid & 63;
        float s, c;
        sincosf(theta[st * (IN_F / 2) + g * 64 + p], &s, &c);
        cs_c[st][p] = c;
        cs_s[st][p] = s;
        pi[st][p] = pairs[st * IN_F + g * GROUP + 2 * p];
        pj[st][p] = pairs[st * IN_F + g * GROUP + 2 * p + 1];
    }
    if (tid < ROWS_PB) {
        int gi = (row0 + tid) * NGROUPS + g;
        qs[tid] = fminf(fmaxf(q_scale[gi], 1e-5f), 1e5f);
        qz[tid] = fminf(fmaxf(-rintf(q_zp[gi]), 0.0f), QMAXF);
    }
    __syncthreads();

    for (int idx = tid; idx < ROWS_PB * (GROUP / 4); idx += 256) {
        int r  = idx >> 5;
        int c4 = (idx & 31) * 4;
        float4 v = *reinterpret_cast<const float4*>(
            weight + (size_t)(row0 + r) * IN_F + g * GROUP + c4);
        v.x *= csc[c4];
        v.y *= csc[c4 + 1];
        v.z *= csc[c4 + 2];
        v.w *= csc[c4 + 3];
        *reinterpret_cast<float4*>(&w[r][c4]) = v;
    }
    __syncthreads();

    #pragma unroll
    for (int st = 0; st < N_STAGES; st++) {
        for (int t = tid; t < ROWS_PB * 64; t += 256) {
            int r = t >> 6, p = t & 63;
            float c = cs_c[st][p], s = cs_s[st][p];
            int i = pi[st][p], j = pj[st][p];
            float xi = w[r][i], xj = w[r][j];
            w[r][i] =  xi * c + xj * s;
            w[r][j] = -xi * s + xj * c;
        }
        __syncthreads();
    }

    for (int t = tid; t < ROWS_PB * GROUP; t += 256) {
        int r = t >> 7, c = t & 127;
        float s = qs[r], rzp = qz[r];
        float q = rintf(w[r][c] / s) + rzp;
        q = fminf(fmaxf(q, 0.0f), QMAXF);
        w[r][c] = (q - rzp) * s;
    }
    __syncthreads();

    #pragma unroll
    for (int st = N_STAGES - 1; st >= 0; st--) {
        for (int t = tid; t < ROWS_PB * 64; t += 256) {
            int r = t >> 6, p = t & 63;
            float c = cs_c[st][p], s = cs_s[st][p];
            int i = pi[st][p], j = pj[st][p];
            float xi = w[r][i], xj = w[r][j];
            w[r][i] = xi * c - xj * s;
            w[r][j] = xi * s + xj * c;
        }
        __syncthreads();
    }

    for (int t = tid; t < ROWS_PB * (GROUP / 2); t += 256) {
        int r  = t >> 6;
        int c2 = (t & 63) * 2;
        float a = w[r][c2]     / csc[c2];
        float b = w[r][c2 + 1] / csc[c2 + 1];
        *reinterpret_cast<__half2*>(
            g_w_h + (size_t)(row0 + r) * IN_F + g * GROUP + c2) =
            __floats2half2_rn(a, b);
    }
}

// ---------------------------------------------------------------------------
// Kernel 2: fp16 mma.sync GEMM (unchanged from R7 — best measured config).
// CTA 128x256, 512 threads, warp tile 64x32, BK=64, 4-stage cp.async.
// ---------------------------------------------------------------------------
#define BM 128
#define BN 256
#define BK 64
#define KSTAGES 4
#define NTHREADS 512
#define A_STAGE_BYTES (BM * BK * 2)
#define B_STAGE_BYTES (BN * BK * 2)
#define STAGE_BYTES   (A_STAGE_BYTES + B_STAGE_BYTES)
#define GEMM_SMEM     (KSTAGES * STAGE_BYTES)            // 196608
#define NKT           (IN_F / BK)                        // 64

__device__ __forceinline__ uint32_t smem_u32(const void* p) {
    uint32_t a;
    asm("{ .reg .u64 t; cvta.to.shared.u64 t, %1; cvt.u32.u64 %0, t; }"
        : "=r"(a) : "l"(p));
    return a;
}
__device__ __forceinline__ void cp_async16(uint32_t saddr, const void* gptr) {
    asm volatile("cp.async.cg.shared.global [%0], [%1], 16;"
                 :: "r"(saddr), "l"(gptr));
}
#define CP_COMMIT() asm volatile("cp.async.commit_group;" ::: "memory")
#define CP_WAIT(n)  asm volatile("cp.async.wait_group %0;" :: "n"(n) : "memory")

__device__ __forceinline__ void ldmatrix_x4(uint32_t* r, uint32_t addr) {
    asm volatile("ldmatrix.sync.aligned.m8n8.x4.shared.b16 {%0,%1,%2,%3}, [%4];"
                 : "=r"(r[0]), "=r"(r[1]), "=r"(r[2]), "=r"(r[3]) : "r"(addr));
}
__device__ __forceinline__ void mma16816(float* c, const uint32_t* a,
                                         const uint32_t* b) {
    asm volatile("mma.sync.aligned.m16n8k16.row.col.f32.f16.f16.f32 "
                 "{%0,%1,%2,%3}, {%4,%5,%6,%7}, {%8,%9}, {%0,%1,%2,%3};"
                 : "+f"(c[0]), "+f"(c[1]), "+f"(c[2]), "+f"(c[3])
                 : "r"(a[0]), "r"(a[1]), "r"(a[2]), "r"(a[3]),
                   "r"(b[0]), "r"(b[1]));
}

__global__ __launch_bounds__(NTHREADS, 1) void gemm_mma_kernel(
    const float* __restrict__ bias, float* __restrict__ C)
{
    extern __shared__ char smem[];
    const uint32_t sbase = smem_u32(smem);
    const int tid  = threadIdx.x;
    const int wid  = tid >> 5;
    const int lane = tid & 31;
    const int bn = blockIdx.x;
    const int bm = blockIdx.y;
    const int warp_m = wid >> 3;
    const int warp_n = wid & 7;

    const __half* Ag0 = g_x_h + (size_t)(bm * BM) * IN_F;
    const __half* Bg0 = g_w_h + (size_t)(bn * BN) * IN_F;

    float acc[4][4][4];
    #pragma unroll
    for (int i = 0; i < 4; i++)
        #pragma unroll
        for (int j = 0; j < 4; j++)
            #pragma unroll
            for (int k = 0; k < 4; k++) acc[i][j][k] = 0.0f;

    auto load_stage = [&](int kt) {
        const int buf = kt & (KSTAGES - 1);
        const int ko  = kt * BK;
        const __half* Ag = Ag0 + ko;
        const __half* Bg = Bg0 + ko;
        const uint32_t sA = sbase + buf * STAGE_BYTES;
        const uint32_t sB = sA + A_STAGE_BYTES;
        #pragma unroll
        for (int t = 0; t < 2; t++) {
            int v = tid + t * NTHREADS;
            int r = v >> 3, c = v & 7;
            uint32_t off = (uint32_t)(r << 7) + (uint32_t)((c ^ (r & 7)) << 4);
            cp_async16(sA + off, Ag + (size_t)r * IN_F + c * 8);
        }
        #pragma unroll
        for (int t = 0; t < 4; t++) {
            int v = tid + t * NTHREADS;
            int r = v >> 3, c = v & 7;
            uint32_t off = (uint32_t)(r << 7) + (uint32_t)((c ^ (r & 7)) << 4);
            cp_async16(sB + off, Bg + (size_t)r * IN_F + c * 8);
        }
    };

    const int m_lane  = warp_m * 64 + (lane & 15);
    const int a_half  = lane >> 4;
    const int xa      = m_lane & 7;
    const int n_lane  = warp_n * 32 + (lane & 7) + ((lane >> 4) << 3);
    const int b_half  = (lane >> 3) & 1;
    const int xb      = n_lane & 7;

    #pragma unroll
    for (int s = 0; s < KSTAGES - 1; s++) {
        load_stage(s);
        CP_COMMIT();
    }

    for (int kt = 0; kt < NKT; kt++) {
        CP_WAIT(KSTAGES - 2);
        __syncthreads();

        if (kt + KSTAGES - 1 < NKT) load_stage(kt + KSTAGES - 1);
        CP_COMMIT();

        const int buf = kt & (KSTAGES - 1);
        const uint32_t sA = sbase + buf * STAGE_BYTES;
        const uint32_t sB = sA + A_STAGE_BYTES;
        const uint32_t aRow = sA + (uint32_t)(m_lane << 7);
        const uint32_t bRow = sB + (uint32_t)(n_lane << 7);

        #pragma unroll
        for (int kk = 0; kk < 4; kk++) {
            uint32_t a_frag[4][4];
            uint32_t b_frag[2][4];
            const uint32_t ac = (uint32_t)(((kk * 2 + a_half) ^ xa) << 4);
            const uint32_t bc = (uint32_t)(((kk * 2 + b_half) ^ xb) << 4);
            #pragma unroll
            for (int mt = 0; mt < 4; mt++)
                ldmatrix_x4(a_frag[mt], aRow + (uint32_t)(mt << 11) + ac);
            #pragma unroll
            for (int nt = 0; nt < 2; nt++)
                ldmatrix_x4(b_frag[nt], bRow + (uint32_t)(nt << 11) + bc);
            #pragma unroll
            for (int mt = 0; mt < 4; mt++) {
                #pragma unroll
                for (int nt = 0; nt < 2; nt++) {
                    mma16816(acc[mt][2 * nt],     a_frag[mt], &b_frag[nt][0]);
                    mma16816(acc[mt][2 * nt + 1], a_frag[mt], &b_frag[nt][2]);
                }
            }
        }
    }

    const int row_base = bm * BM + warp_m * 64 + (lane >> 2);
    const int col_base = bn * BN + warp_n * 32 + 2 * (lane & 3);
    #pragma unroll
    for (int mt = 0; mt < 4; mt++) {
        const int r0 = row_base + mt * 16;
        #pragma unroll
        for (int n8 = 0; n8 < 4; n8++) {
            const int col = col_base + n8 * 8;
            float2 bv = *reinterpret_cast<const float2*>(bias + col);
            float2 o0, o1;
            o0.x = acc[mt][n8][0] + bv.x;
            o0.y = acc[mt][n8][1] + bv.y;
            o1.x = acc[mt][n8][2] + bv.x;
            o1.y = acc[mt][n8][3] + bv.y;
            *reinterpret_cast<float2*>(C + (size_t)r0 * OUT_F + col)       = o0;
            *reinterpret_cast<float2*>(C + (size_t)(r0 + 8) * OUT_F + col) = o1;
        }
    }
}

// ---------------------------------------------------------------------------
// Launch
// ---------------------------------------------------------------------------
extern "C" void kernel_launch(void* const* d_in, const int* in_sizes, int n_in,
                              void* d_out, int out_size)
{
    const float* x              = (const float*)d_in[0];
    const float* weight         = (const float*)d_in[1];
    const float* bias           = (const float*)d_in[2];
    const float* channel_scales = (const float*)d_in[3];
    const float* theta          = (const float*)d_in[4];
    const float* q_scale        = (const float*)d_in[5];
    const float* q_zp           = (const float*)d_in[6];
    const int*   pairs          = (const int*)d_in[7];
    float* out = (float*)d_out;

    cudaFuncSetAttribute(gemm_mma_kernel,
                         cudaFuncAttributeMaxDynamicSharedMemorySize, GEMM_SMEM);

    dim3 tgrid(NGROUPS, OUT_F / ROWS_PB);
    transform_kernel<<<tgrid, 256>>>(weight, channel_scales, theta,
                                     q_scale, q_zp, pairs, x);

    dim3 grid(OUT_F / BN, N_TOK / BM);
    gemm_mma_kernel<<<grid, NTHREADS, GEMM_SMEM>>>(bias, out);
}

// round 10
// speedup vs baseline: 1.1172x; 1.0503x over previous
#include <cuda_runtime.h>
#include <cuda_fp16.h>
#include <cstdint>

#define IN_F     4096
#define OUT_F    4096
#define N_TOK    8192
#define GROUP    128
#define NGROUPS  (IN_F / GROUP)
#define N_STAGES 4
#define QMAXF    15.0f

// ---------------- scratch (device globals; no runtime allocation) ----------
__device__ __half g_w_h[(size_t)OUT_F * IN_F];
__device__ __half g_x_h[(size_t)N_TOK * IN_F];

// ---------------------------------------------------------------------------
// Kernel 1: fused weight transform + x->fp16 conversion.
// Block = (group g, 64 rows); 8 warps, each warp owns 8 rows (16 independent
// rotations per lane per stage -> high ILP) with __syncwarp-only stage sync.
// Each block also converts a disjoint 16384-elem slice of x up front.
// ---------------------------------------------------------------------------
#define ROWS_PB 64
#define WPAD    132
#define TBLOCKS (NGROUPS * (OUT_F / ROWS_PB))          // 2048
#define XCHUNK  ((size_t)N_TOK * IN_F / TBLOCKS)       // 16384 elems / block

__global__ __launch_bounds__(256) void transform_kernel(
    const float* __restrict__ weight,
    const float* __restrict__ channel_scales,
    const float* __restrict__ theta,
    const float* __restrict__ q_scale,
    const float* __restrict__ q_zp,
    const int*   __restrict__ pairs,
    const float* __restrict__ x)
{
    const int g    = blockIdx.x;
    const int row0 = blockIdx.y * ROWS_PB;
    const int tid  = threadIdx.x;
    const int wrp  = tid >> 5;
    const int lane = tid & 31;

    __shared__ float w[ROWS_PB][WPAD];
    __shared__ float cs_c[N_STAGES][64], cs_s[N_STAGES][64];
    __shared__ int   pi[N_STAGES][64], pj[N_STAGES][64];
    __shared__ float csc[GROUP];
    __shared__ float qs[ROWS_PB], qz[ROWS_PB];

    // ---- fused x -> fp16 conversion (independent stream) ----
    {
        const int blk = blockIdx.y * NGROUPS + blockIdx.x;
        const float* xs = x + (size_t)blk * XCHUNK;
        __half* xd = g_x_h + (size_t)blk * XCHUNK;
        #pragma unroll
        for (int t = 0; t < (int)(XCHUNK / (256 * 8)); t++) {
            size_t i = ((size_t)(t * 256 + tid)) * 8;
            float4 v0 = *reinterpret_cast<const float4*>(xs + i);
            float4 v1 = *reinterpret_cast<const float4*>(xs + i + 4);
            __half2 h[4];
            h[0] = __floats2half2_rn(v0.x, v0.y);
            h[1] = __floats2half2_rn(v0.z, v0.w);
            h[2] = __floats2half2_rn(v1.x, v1.y);
            h[3] = __floats2half2_rn(v1.z, v1.w);
            *reinterpret_cast<uint4*>(xd + i) =
                *reinterpret_cast<const uint4*>(h);
        }
    }

    // ---- block-wide tables (one __syncthreads) ----
    if (tid < GROUP) csc[tid] = channel_scales[g * GROUP + tid];
    {
        int st = tid >> 6, p = tid & 63;
        float s, c;
        sincosf(theta[st * (IN_F / 2) + g * 64 + p], &s, &c);
        cs_c[st][p] = c;
        cs_s[st][p] = s;
        pi[st][p] = pairs[st * IN_F + g * GROUP + 2 * p];
        pj[st][p] = pairs[st * IN_F + g * GROUP + 2 * p + 1];
    }
    __syncthreads();

    // ---- per-warp: 8 rows, warp-synchronous ----
    const int rbase = wrp * 8;               // local row base for this warp

    if (lane < 8) {
        int gi = (row0 + rbase + lane) * NGROUPS + g;
        qs[rbase + lane] = fminf(fmaxf(q_scale[gi], 1e-5f), 1e5f);
        qz[rbase + lane] = fminf(fmaxf(-rintf(q_zp[gi]), 0.0f), QMAXF);
    }

    const int c4 = lane * 4;
    #pragma unroll
    for (int rr = 0; rr < 8; rr++) {
        float4 v = *reinterpret_cast<const float4*>(
            weight + (size_t)(row0 + rbase + rr) * IN_F + g * GROUP + c4);
        v.x *= csc[c4];
        v.y *= csc[c4 + 1];
        v.z *= csc[c4 + 2];
        v.w *= csc[c4 + 3];
        *reinterpret_cast<float4*>(&w[rbase + rr][c4]) = v;
    }
    __syncwarp();

    // forward rotations: 16 independent rotations per lane per stage
    #pragma unroll
    for (int st = 0; st < N_STAGES; st++) {
        #pragma unroll
        for (int t = 0; t < 16; t++) {
            int v = lane + t * 32;           // 0..511
            int r = rbase + (v >> 6);
            int p = v & 63;
            float c = cs_c[st][p], s = cs_s[st][p];
            int i = pi[st][p], j = pj[st][p];
            float xi = w[r][i], xj = w[r][j];
            w[r][i] =  xi * c + xj * s;
            w[r][j] = -xi * s + xj * c;
        }
        __syncwarp();
    }

    // quant-dequant
    #pragma unroll
    for (int t = 0; t < 32; t++) {
        int v = lane + t * 32;               // 0..1023
        int r = rbase + (v >> 7);
        int c = v & 127;
        float s = qs[r], rzp = qz[r];
        float q = rintf(w[r][c] / s) + rzp;
        q = fminf(fmaxf(q, 0.0f), QMAXF);
        w[r][c] = (q - rzp) * s;
    }
    __syncwarp();

    // inverse rotations
    #pragma unroll
    for (int st = N_STAGES - 1; st >= 0; st--) {
        #pragma unroll
        for (int t = 0; t < 16; t++) {
            int v = lane + t * 32;
            int r = rbase + (v >> 6);
            int p = v & 63;
            float c = cs_c[st][p], s = cs_s[st][p];
            int i = pi[st][p], j = pj[st][p];
            float xi = w[r][i], xj = w[r][j];
            w[r][i] = xi * c - xj * s;
            w[r][j] = xi * s + xj * c;
        }
        __syncwarp();
    }

    // unscale + fp16 store
    #pragma unroll
    for (int rr = 0; rr < 8; rr++) {
        __half2 h[2];
        h[0] = __floats2half2_rn(w[rbase + rr][c4]     / csc[c4],
                                 w[rbase + rr][c4 + 1] / csc[c4 + 1]);
        h[1] = __floats2half2_rn(w[rbase + rr][c4 + 2] / csc[c4 + 2],
                                 w[rbase + rr][c4 + 3] / csc[c4 + 3]);
        *reinterpret_cast<uint2*>(
            g_w_h + (size_t)(row0 + rbase + rr) * IN_F + g * GROUP + c4) =
            *reinterpret_cast<const uint2*>(h);
    }
}

// ---------------------------------------------------------------------------
// Kernel 2: fp16 mma.sync GEMM. CTA 128x256, 512 threads, warp tile 64x32,
// BK=128 (2-stage, 192KB smem) -> per-iter barrier overhead halved.
// ---------------------------------------------------------------------------
#define BM 128
#define BN 256
#define BK 128
#define KSTAGES 2
#define NTHREADS 512
#define A_STAGE_BYTES (BM * BK * 2)                       // 32768
#define B_STAGE_BYTES (BN * BK * 2)                       // 65536
#define STAGE_BYTES   (A_STAGE_BYTES + B_STAGE_BYTES)     // 98304
#define GEMM_SMEM     (KSTAGES * STAGE_BYTES)             // 196608
#define NKT           (IN_F / BK)                         // 32

__device__ __forceinline__ uint32_t smem_u32(const void* p) {
    uint32_t a;
    asm("{ .reg .u64 t; cvta.to.shared.u64 t, %1; cvt.u32.u64 %0, t; }"
        : "=r"(a) : "l"(p));
    return a;
}
__device__ __forceinline__ void cp_async16(uint32_t saddr, const void* gptr) {
    asm volatile("cp.async.cg.shared.global [%0], [%1], 16;"
                 :: "r"(saddr), "l"(gptr));
}
#define CP_COMMIT() asm volatile("cp.async.commit_group;" ::: "memory")
#define CP_WAIT(n)  asm volatile("cp.async.wait_group %0;" :: "n"(n) : "memory")

__device__ __forceinline__ void ldmatrix_x4(uint32_t* r, uint32_t addr) {
    asm volatile("ldmatrix.sync.aligned.m8n8.x4.shared.b16 {%0,%1,%2,%3}, [%4];"
                 : "=r"(r[0]), "=r"(r[1]), "=r"(r[2]), "=r"(r[3]) : "r"(addr));
}
__device__ __forceinline__ void mma16816(float* c, const uint32_t* a,
                                         const uint32_t* b) {
    asm volatile("mma.sync.aligned.m16n8k16.row.col.f32.f16.f16.f32 "
                 "{%0,%1,%2,%3}, {%4,%5,%6,%7}, {%8,%9}, {%0,%1,%2,%3};"
                 : "+f"(c[0]), "+f"(c[1]), "+f"(c[2]), "+f"(c[3])
                 : "r"(a[0]), "r"(a[1]), "r"(a[2]), "r"(a[3]),
                   "r"(b[0]), "r"(b[1]));
}

__global__ __launch_bounds__(NTHREADS, 1) void gemm_mma_kernel(
    const float* __restrict__ bias, float* __restrict__ C)
{
    extern __shared__ char smem[];
    const uint32_t sbase = smem_u32(smem);
    const int tid  = threadIdx.x;
    const int wid  = tid >> 5;
    const int lane = tid & 31;
    const int bn = blockIdx.x;
    const int bm = blockIdx.y;
    const int warp_m = wid >> 3;
    const int warp_n = wid & 7;

    const __half* Ag0 = g_x_h + (size_t)(bm * BM) * IN_F;
    const __half* Bg0 = g_w_h + (size_t)(bn * BN) * IN_F;

    float acc[4][4][4];
    #pragma unroll
    for (int i = 0; i < 4; i++)
        #pragma unroll
        for (int j = 0; j < 4; j++)
            #pragma unroll
            for (int k = 0; k < 4; k++) acc[i][j][k] = 0.0f;

    // rows are 256B wide now: 16 chunks of 16B per row
    auto load_stage = [&](int kt) {
        const int buf = kt & (KSTAGES - 1);
        const int ko  = kt * BK;
        const __half* Ag = Ag0 + ko;
        const __half* Bg = Bg0 + ko;
        const uint32_t sA = sbase + buf * STAGE_BYTES;
        const uint32_t sB = sA + A_STAGE_BYTES;
        #pragma unroll
        for (int t = 0; t < 4; t++) {        // A: 2048 chunks / 512 thr
            int v = tid + t * NTHREADS;
            int r = v >> 4, c = v & 15;
            uint32_t off = (uint32_t)(r << 8) + (uint32_t)((c ^ (r & 7)) << 4);
            cp_async16(sA + off, Ag + (size_t)r * IN_F + c * 8);
        }
        #pragma unroll
        for (int t = 0; t < 8; t++) {        // B: 4096 chunks / 512 thr
            int v = tid + t * NTHREADS;
            int r = v >> 4, c = v & 15;
            uint32_t off = (uint32_t)(r << 8) + (uint32_t)((c ^ (r & 7)) << 4);
            cp_async16(sB + off, Bg + (size_t)r * IN_F + c * 8);
        }
    };

    const int m_lane  = warp_m * 64 + (lane & 15);
    const int a_half  = lane >> 4;
    const int xa      = m_lane & 7;
    const int n_lane  = warp_n * 32 + (lane & 7) + ((lane >> 4) << 3);
    const int b_half  = (lane >> 3) & 1;
    const int xb      = n_lane & 7;

    load_stage(0);
    CP_COMMIT();

    for (int kt = 0; kt < NKT; kt++) {
        CP_WAIT(0);
        __syncthreads();

        if (kt + 1 < NKT) load_stage(kt + 1);
        CP_COMMIT();

        const int buf = kt & (KSTAGES - 1);
        const uint32_t sA = sbase + buf * STAGE_BYTES;
        const uint32_t sB = sA + A_STAGE_BYTES;
        const uint32_t aRow = sA + (uint32_t)(m_lane << 8);
        const uint32_t bRow = sB + (uint32_t)(n_lane << 8);

        #pragma unroll
        for (int kk = 0; kk < 8; kk++) {
            uint32_t a_frag[4][4];
            uint32_t b_frag[2][4];
            const uint32_t ac = (uint32_t)(((kk * 2 + a_half) ^ xa) << 4);
            const uint32_t bc = (uint32_t)(((kk * 2 + b_half) ^ xb) << 4);
            #pragma unroll
            for (int mt = 0; mt < 4; mt++)
                ldmatrix_x4(a_frag[mt], aRow + (uint32_t)(mt << 12) + ac);
            #pragma unroll
            for (int nt = 0; nt < 2; nt++)
                ldmatrix_x4(b_frag[nt], bRow + (uint32_t)(nt << 12) + bc);
            #pragma unroll
            for (int mt = 0; mt < 4; mt++) {
                #pragma unroll
                for (int nt = 0; nt < 2; nt++) {
                    mma16816(acc[mt][2 * nt],     a_frag[mt], &b_frag[nt][0]);
                    mma16816(acc[mt][2 * nt + 1], a_frag[mt], &b_frag[nt][2]);
                }
            }
        }
    }

    const int row_base = bm * BM + warp_m * 64 + (lane >> 2);
    const int col_base = bn * BN + warp_n * 32 + 2 * (lane & 3);
    #pragma unroll
    for (int mt = 0; mt < 4; mt++) {
        const int r0 = row_base + mt * 16;
        #pragma unroll
        for (int n8 = 0; n8 < 4; n8++) {
            const int col = col_base + n8 * 8;
            float2 bv = *reinterpret_cast<const float2*>(bias + col);
            float2 o0, o1;
            o0.x = acc[mt][n8][0] + bv.x;
            o0.y = acc[mt][n8][1] + bv.y;
            o1.x = acc[mt][n8][2] + bv.x;
            o1.y = acc[mt][n8][3] + bv.y;
            *reinterpret_cast<float2*>(C + (size_t)r0 * OUT_F + col)       = o0;
            *reinterpret_cast<float2*>(C + (size_t)(r0 + 8) * OUT_F + col) = o1;
        }
    }
}

// ---------------------------------------------------------------------------
// Launch
// ---------------------------------------------------------------------------
extern "C" void kernel_launch(void* const* d_in, const int* in_sizes, int n_in,
                              void* d_out, int out_size)
{
    const float* x              = (const float*)d_in[0];
    const float* weight         = (const float*)d_in[1];
    const float* bias           = (const float*)d_in[2];
    const float* channel_scales = (const float*)d_in[3];
    const float* theta          = (const float*)d_in[4];
    const float* q_scale        = (const float*)d_in[5];
    const float* q_zp           = (const float*)d_in[6];
    const int*   pairs          = (const int*)d_in[7];
    float* out = (float*)d_out;

    cudaFuncSetAttribute(gemm_mma_kernel,
                         cudaFuncAttributeMaxDynamicSharedMemorySize, GEMM_SMEM);

    dim3 tgrid(NGROUPS, OUT_F / ROWS_PB);
    transform_kernel<<<tgrid, 256>>>(weight, channel_scales, theta,
                                     q_scale, q_zp, pairs, x);

    dim3 grid(OUT_F / BN, N_TOK / BM);
    gemm_mma_kernel<<<grid, NTHREADS, GEMM_SMEM>>>(bias, out);
}